// round 15
// baseline (speedup 1.0000x reference)
#include <cuda_runtime.h>
#include <math.h>
#include <string.h>

#define NV 512
#define DIM 256
#define HD 64
#define NVHD (NV*HD)
#define EPSLN 1e-5f
typedef unsigned long long u64;

struct Scratch {
    float Wh1[NV*DIM], Aa[NV*DIM], Bb[NV*DIM];
    float tf[NVHD], tfp[4][NVHD], cfp[4][NVHD];
    float E[NV], Dinv[NV];
    float Np0[NV*DIM], Np1[NV*DIM], Np2[NV*DIM], Np3[NV*DIM];
    float wc[DIM];
    float mb[64], seb[64], gpart[64*DIM];
    float H3[NVHD], h4[HD];
    float Wf[448*DIM];
    float bias2[DIM];
    float opp[8][NV*DIM];
};
__device__ Scratch g_s;

__device__ __forceinline__ float ninf() { return __int_as_float(0xff800000); }
__device__ __forceinline__ u64 pk2(float x) { u64 r; asm("mov.b64 %0,{%1,%1};":"=l"(r):"f"(x)); return r; }
__device__ __forceinline__ u64 pk2x(float a, float b) { u64 r; asm("mov.b64 %0,{%1,%2};":"=l"(r):"f"(a),"f"(b)); return r; }
__device__ __forceinline__ u64 f2u(float2 v) { u64 r; memcpy(&r, &v, 8); return r; }
__device__ __forceinline__ void upk(u64 v, float& lo, float& hi) { asm("mov.b64 {%0,%1},%2;":"=f"(lo),"=f"(hi):"l"(v)); }
__device__ __forceinline__ void fma2(u64& acc, u64 a, u64 b) { asm("fma.rn.f32x2 %0,%1,%2,%0;":"+l"(acc):"l"(a),"l"(b)); }
__device__ __forceinline__ u64 add2(u64 a, u64 b) { u64 r; asm("add.rn.f32x2 %0,%1,%2;":"=l"(r):"l"(a),"l"(b)); return r; }
__device__ __forceinline__ void rfma2(u64& acc, u64 a, u64 b, u64 wh) {
    u64 t = add2(a, b);
    u64 u = add2(t, t & 0x7FFFFFFF7FFFFFFFULL);
    asm("fma.rn.f32x2 %0,%1,%2,%0;":"+l"(acc):"l"(u),"l"(wh));
}

// ---------- loaders ----------
struct LdA { const float* A; int ld;
    __device__ __forceinline__ float operator()(int i, int k) const { return A[i*ld + k]; } };
struct LdW2g { const float* A;
    __device__ __forceinline__ float operator()(int i, int k) const {
        return (i < 385) ? A[i*DIM + k] : 0.f; } };
struct LdAdjE { const int* a; const float* E;
    __device__ __forceinline__ float operator()(int i, int k) const {
        return (float)a[i*NV + k] * E[k]; } };
struct LdXt { const float *V, *ph;
    __device__ __forceinline__ float operator()(int i, int k) const {
        return (k < DIM) ? V[i*DIM + k] : ph[i*DIM + k - DIM]; } };
struct LdCi { const float* V; const int *n0, *n1, *va; int bi;
    __device__ __forceinline__ float operator()(int i, int k) const {
        if (k < DIM) return V[i*DIM + k];
        int r = i - bi;
        if (!va[r]) return 0.f;
        return (k < 2*DIM) ? V[n0[r]*DIM + k - DIM] : V[n1[r]*DIM + k - 2*DIM]; } };
struct LdHcat { const float *n0, *n1, *n2, *n3, *Di, *H3, *h4;
    __device__ __forceinline__ float operator()(int i, int c) const {
        if (c < 256) return (n0[i*DIM+c] + n1[i*DIM+c] + n2[i*DIM+c] + n3[i*DIM+c]) * Di[i];
        if (c < 384) return H3[i*HD + (c - 320)];
        return (i < HD) ? h4[i] : 0.f; } };

// ---------- 64x64 GEMM tile, packed FFMA2, double-buffered smem (buf: 4352 floats) ----------
template <class FA>
__device__ __forceinline__ void gemm_core(const FA& loadA, const float* __restrict__ W,
                                          const float* __restrict__ bias, float* __restrict__ C,
                                          int Nn, int kbeg, int kend, int relu,
                                          int bi, int bj, float* buf) {
    float (*sA)[16][68] = (float(*)[16][68])buf;
    float (*sW)[16][68] = (float(*)[16][68])(buf + 2*16*68);
    int tid = threadIdx.x, tx = tid & 15, ty = tid >> 4;
    u64 a01c[4], a23c[4];
#pragma unroll
    for (int c = 0; c < 4; c++) { a01c[c] = 0ULL; a23c[c] = 0ULL; }
    int nIter = (kend - kbeg + 15) >> 4;
    float rA[4], rW[4];
#pragma unroll
    for (int p = 0; p < 4; p++) {
        int t = tid + p*256;
        int ia = t >> 4, ka = t & 15, kk = kbeg + ka;
        rA[p] = (kk < kend) ? loadA(bi + ia, kk) : 0.f;
        int kw = t >> 6, jw = t & 63, k2 = kbeg + kw;
        rW[p] = (k2 < kend) ? W[k2 * Nn + bj + jw] : 0.f;
    }
#pragma unroll
    for (int p = 0; p < 4; p++) {
        int t = tid + p*256;
        sA[0][t & 15][t >> 4] = rA[p];
        sW[0][t >> 6][t & 63] = rW[p];
    }
    __syncthreads();
    for (int it = 0; it < nIter; it++) {
        int cur = it & 1;
        if (it + 1 < nIter) {
            int k0n = kbeg + (it + 1) * 16;
#pragma unroll
            for (int p = 0; p < 4; p++) {
                int t = tid + p*256;
                int ia = t >> 4, ka = t & 15, kk = k0n + ka;
                rA[p] = (kk < kend) ? loadA(bi + ia, kk) : 0.f;
                int kw = t >> 6, jw = t & 63, k2 = k0n + kw;
                rW[p] = (k2 < kend) ? W[k2 * Nn + bj + jw] : 0.f;
            }
        }
#pragma unroll
        for (int k = 0; k < 16; k++) {
            float4 av = *(float4*)&sA[cur][k][ty*4];
            u64 a01 = pk2x(av.x, av.y);
            u64 a23 = pk2x(av.z, av.w);
            float4 wv = *(float4*)&sW[cur][k][tx*4];
            u64 b0 = pk2(wv.x), b1 = pk2(wv.y), b2 = pk2(wv.z), b3 = pk2(wv.w);
            fma2(a01c[0], a01, b0); fma2(a01c[1], a01, b1);
            fma2(a01c[2], a01, b2); fma2(a01c[3], a01, b3);
            fma2(a23c[0], a23, b0); fma2(a23c[1], a23, b1);
            fma2(a23c[2], a23, b2); fma2(a23c[3], a23, b3);
        }
        if (it + 1 < nIter) {
            int nxt = cur ^ 1;
#pragma unroll
            for (int p = 0; p < 4; p++) {
                int t = tid + p*256;
                sA[nxt][t & 15][t >> 4] = rA[p];
                sW[nxt][t >> 6][t & 63] = rW[p];
            }
            __syncthreads();
        }
    }
    float acc[4][4];
#pragma unroll
    for (int c = 0; c < 4; c++) {
        upk(a01c[c], acc[0][c], acc[1][c]);
        upk(a23c[c], acc[2][c], acc[3][c]);
    }
#pragma unroll
    for (int r = 0; r < 4; r++) {
        int i = bi + ty*4 + r;
#pragma unroll
        for (int c = 0; c < 4; c++) {
            int j = bj + tx*4 + c;
            float v = acc[r][c];
            if (bias) v += bias[j];
            if (relu) v = fmaxf(v, 0.f);
            C[i * Nn + j] = v;
        }
    }
}

// ---------- fused 2-layer MLP partial: out = relu(X@W1c + b1)@W2c (+b2) ----------
// buf: 8704 floats. W1c: rows K, ld=DIM (pre-offset to col chunk). W2c: 64xHD chunk.
template <class FA>
__device__ __forceinline__ void fused_mlp(const FA& loadX, const float* __restrict__ W1c,
                                          const float* __restrict__ b1,
                                          const float* __restrict__ W2c,
                                          const float* __restrict__ b2,
                                          float* __restrict__ out,
                                          int K, int bi, float* buf) {
    float (*sA)[16][68] = (float(*)[16][68])buf;
    float (*sW)[16][68] = (float(*)[16][68])(buf + 2*16*68);
    float (*R)[68] = (float(*)[68])(buf + 4352);
    int tid = threadIdx.x, tx = tid & 15, ty = tid >> 4;
    u64 a01c[4], a23c[4];
#pragma unroll
    for (int c = 0; c < 4; c++) { a01c[c] = 0ULL; a23c[c] = 0ULL; }
    int nIter = K >> 4;
    float rA[4], rW[4];
#pragma unroll
    for (int p = 0; p < 4; p++) {
        int t = tid + p*256;
        rA[p] = loadX(bi + (t >> 4), t & 15);
        rW[p] = W1c[(t >> 6) * DIM + (t & 63)];
    }
#pragma unroll
    for (int p = 0; p < 4; p++) {
        int t = tid + p*256;
        sA[0][t & 15][t >> 4] = rA[p];
        sW[0][t >> 6][t & 63] = rW[p];
    }
    __syncthreads();
    for (int it = 0; it < nIter; it++) {
        int cur = it & 1;
        if (it + 1 < nIter) {
            int k0n = (it + 1) * 16;
#pragma unroll
            for (int p = 0; p < 4; p++) {
                int t = tid + p*256;
                rA[p] = loadX(bi + (t >> 4), k0n + (t & 15));
                rW[p] = W1c[(k0n + (t >> 6)) * DIM + (t & 63)];
            }
        }
#pragma unroll
        for (int k = 0; k < 16; k++) {
            float4 av = *(float4*)&sA[cur][k][ty*4];
            u64 a01 = pk2x(av.x, av.y);
            u64 a23 = pk2x(av.z, av.w);
            float4 wv = *(float4*)&sW[cur][k][tx*4];
            u64 b0 = pk2(wv.x), b1v = pk2(wv.y), b2v = pk2(wv.z), b3 = pk2(wv.w);
            fma2(a01c[0], a01, b0); fma2(a01c[1], a01, b1v);
            fma2(a01c[2], a01, b2v); fma2(a01c[3], a01, b3);
            fma2(a23c[0], a23, b0); fma2(a23c[1], a23, b1v);
            fma2(a23c[2], a23, b2v); fma2(a23c[3], a23, b3);
        }
        if (it + 1 < nIter) {
            int nxt = cur ^ 1;
#pragma unroll
            for (int p = 0; p < 4; p++) {
                int t = tid + p*256;
                sA[nxt][t & 15][t >> 4] = rA[p];
                sW[nxt][t >> 6][t & 63] = rW[p];
            }
            __syncthreads();
        }
    }
    {
        float acc[4][4];
#pragma unroll
        for (int c = 0; c < 4; c++) {
            upk(a01c[c], acc[0][c], acc[1][c]);
            upk(a23c[c], acc[2][c], acc[3][c]);
        }
        __syncthreads();
#pragma unroll
        for (int r = 0; r < 4; r++)
#pragma unroll
            for (int c = 0; c < 4; c++)
                R[ty*4 + r][tx*4 + c] = fmaxf(acc[r][c] + b1[tx*4 + c], 0.f);
    }
    __syncthreads();
    // stage B: R(64x64) @ W2c(64xHD)
    float (*sW2)[68] = (float(*)[68])buf;
#pragma unroll
    for (int p = 0; p < 16; p++) {
        int t = tid + p*256;
        sW2[t >> 6][t & 63] = W2c[(t >> 6) * HD + (t & 63)];
    }
    __syncthreads();
    float acc2[4][4];
#pragma unroll
    for (int r = 0; r < 4; r++)
#pragma unroll
        for (int c = 0; c < 4; c++) acc2[r][c] = 0.f;
    for (int k = 0; k < 64; k++) {
        float a0 = R[ty*4+0][k], a1 = R[ty*4+1][k], a2 = R[ty*4+2][k], a3 = R[ty*4+3][k];
        float4 wv = *(float4*)&sW2[k][tx*4];
        acc2[0][0] += a0*wv.x; acc2[0][1] += a0*wv.y; acc2[0][2] += a0*wv.z; acc2[0][3] += a0*wv.w;
        acc2[1][0] += a1*wv.x; acc2[1][1] += a1*wv.y; acc2[1][2] += a1*wv.z; acc2[1][3] += a1*wv.w;
        acc2[2][0] += a2*wv.x; acc2[2][1] += a2*wv.y; acc2[2][2] += a2*wv.z; acc2[2][3] += a2*wv.w;
        acc2[3][0] += a3*wv.x; acc2[3][1] += a3*wv.y; acc2[3][2] += a3*wv.z; acc2[3][3] += a3*wv.w;
    }
#pragma unroll
    for (int r = 0; r < 4; r++)
#pragma unroll
        for (int c = 0; c < 4; c++) {
            int j = tx*4 + c;
            out[(bi + ty*4 + r)*HD + j] = acc2[r][c] + (b2 ? b2[j] : 0.f);
        }
}

// ---------- Wave 1, 197 CTAs ----------
struct W1P {
    const float *V, *ph, *W1, *cew1, *ceb1, *tew1, *teb1, *tew2, *teb2,
                *cow1, *cob1, *cow2, *cob2, *cew2, *ac0, *ac1, *W2, *Wo, *astd1;
    const int* adj;
    float *Wh1, *Aa, *Bb, *wc, *Wf, *E, *tfp, *cfp;
};
__global__ void __launch_bounds__(256) k_w1(W1P p) {
    __shared__ __align__(16) float buf[8704];
    __shared__ int sn0[64], sn1[64], sva[64];
    int b = blockIdx.x, tid = threadIdx.x;
    if (b < 32) {
        // cfp partial: rb=q>>2, kc=q&3 (longest -> first)
        int rb = b >> 2, kc = b & 3, bi = rb * 64;
        int warp = tid >> 5, lane = tid & 31;
#pragma unroll
        for (int rr = 0; rr < 8; rr++) {
            int r = warp*8 + rr, i = bi + r;
            int found = 0, a0 = 0, a1 = 0;
            for (int base = 0; base < NV && found < 2; base += 32) {
                int a = p.adj[i*NV + base + lane];
                unsigned m = __ballot_sync(0xffffffffu, a == 1);
                while (m && found < 2) {
                    int bb = __ffs(m) - 1;
                    if (!found) a0 = base + bb; else a1 = base + bb;
                    found++;
                    m &= m - 1;
                }
            }
            if (lane == 0) { sn0[r] = a0; sn1[r] = a1; sva[r] = (found == 2); }
        }
        __syncthreads();
        fused_mlp(LdCi{p.V, sn0, sn1, sva, bi}, p.cow1 + kc*64, p.cob1 + kc*64,
                  p.cow2 + kc*64*HD, (kc == 0) ? p.cob2 : nullptr,
                  p.cfp + kc*NVHD, 3*DIM, bi, buf);
    } else if (b < 64) {
        int q = b - 32, rb = q >> 2, kc = q & 3, bi = rb * 64;
        fused_mlp(LdXt{p.V, p.ph}, p.tew1 + kc*64, p.teb1 + kc*64,
                  p.tew2 + kc*64*HD, (kc == 0) ? p.teb2 : nullptr,
                  p.tfp + kc*NVHD, 2*DIM, bi, buf);
    } else if (b < 96) {
        int q = b - 64;
        gemm_core(LdA{p.V, DIM}, p.W1, nullptr, p.Wh1, DIM, 0, DIM, 0, (q>>2)*64, (q&3)*64, buf);
    } else if (b < 128) {
        int q = b - 96;
        gemm_core(LdA{p.V, DIM}, p.cew1, p.ceb1, p.Aa, DIM, 0, DIM, 0, (q>>2)*64, (q&3)*64, buf);
    } else if (b < 160) {
        int q = b - 128;
        gemm_core(LdA{p.V, DIM}, p.cew1 + DIM*DIM, nullptr, p.Bb, DIM, 0, DIM, 0, (q>>2)*64, (q&3)*64, buf);
    } else if (b == 160) {
        if (tid < HD) buf[tid] = p.ac0[tid] + p.ac1[tid];
        __syncthreads();
        float s = 0.f;
        for (int d = 0; d < HD; d++) s += p.cew2[tid*HD + d] * buf[d];
        p.wc[tid] = s;
    } else if (b < 189) {
        int q = b - 161;
        gemm_core(LdW2g{p.W2}, p.Wo, nullptr, p.Wf, DIM, 0, DIM, 0, (q>>2)*64, (q&3)*64, buf);
    } else {
        // E = exp(V @ (W1 @ a_std1)), 8 CTAs x 64 rows
        int eb = b - 189;
        float s = 0.f;
        for (int j = 0; j < DIM; j++) s += p.W1[tid*DIM + j] * p.astd1[j];
        buf[tid] = s;
        __syncthreads();
        int warp = tid >> 5, lane = tid & 31;
#pragma unroll
        for (int rr = 0; rr < 8; rr++) {
            int w = eb*64 + warp*8 + rr;
            float pr = 0.f;
            for (int k = lane; k < DIM; k += 32) pr += p.V[w*DIM + k] * buf[k];
#pragma unroll
            for (int o = 16; o; o >>= 1) pr += __shfl_xor_sync(0xffffffffu, pr, o);
            if (lane == 0) p.E[w] = expf(pr);
        }
    }
}

// ---------- Wave 2: pairFused(64) + H3 + h4 + Np(128) + vecD(64), 258 CTAs ----------
struct W2P {
    const float *Aa, *Bb, *wc, *Wh1, *E, *tfp, *cfp;
    const int* adj;
    float *mb, *seb, *gpart, *tf, *H3, *h4, *Np0, *Np1, *Np2, *Np3, *Dinv;
};
__global__ void __launch_bounds__(256) k_w2(W2P p) {
    __shared__ __align__(16) float buf[4896];
    int bid = blockIdx.x, tid = threadIdx.x;
    if (bid < 64) {
        // fused pair: full-K scores, stats, weighted features
        float (*sA)[68] = (float(*)[68])buf;
        float (*sB)[68] = (float(*)[68])(buf + 32*68);
        float* red = buf + 64*68;   // 256
        float* gsh = red + 256;     // 256
        float* swc = gsh + 256;     // 32
        int b = bid;
        int bi = (b >> 3) * 64, bj = (b & 7) * 64;
        int tx = tid & 15, ty = tid >> 4;
        int warp = tid >> 5, lane = tid & 31;
        u64 acc[4][2];
#pragma unroll
        for (int r = 0; r < 4; r++) { acc[r][0] = 0ULL; acc[r][1] = 0ULL; }

        for (int k0 = 0; k0 < DIM; k0 += 32) {
#pragma unroll
            for (int q = 0; q < 8; q++) {
                int t = tid + q * 256;
                int i = t >> 5, k = t & 31;
                sA[k][i] = p.Aa[(bi + i) * DIM + k0 + k];
                sB[k][i] = p.Bb[(bj + i) * DIM + k0 + k];
            }
            if (tid < 32) swc[tid] = p.wc[k0 + tid] * 0.5f;
            __syncthreads();
#pragma unroll
            for (int k = 0; k < 32; k++) {
                u64 wh = pk2(swc[k]);
                float4 av = *(float4*)&sA[k][ty*4];
                u64 A0 = pk2(av.x), A1 = pk2(av.y), A2 = pk2(av.z), A3 = pk2(av.w);
                u64 B01 = f2u(*(float2*)&sB[k][tx*4]);
                u64 B23 = f2u(*(float2*)&sB[k][tx*4 + 2]);
                rfma2(acc[0][0], A0, B01, wh); rfma2(acc[0][1], A0, B23, wh);
                rfma2(acc[1][0], A1, B01, wh); rfma2(acc[1][1], A1, B23, wh);
                rfma2(acc[2][0], A2, B01, wh); rfma2(acc[2][1], A2, B23, wh);
                rfma2(acc[3][0], A3, B01, wh); rfma2(acc[3][1], A3, B23, wh);
            }
            __syncthreads();
        }
        float e[4][4];
        float m = ninf();
#pragma unroll
        for (int r = 0; r < 4; r++) {
            int i = bi + ty*4 + r;
            float sv[4];
            upk(acc[r][0], sv[0], sv[1]); upk(acc[r][1], sv[2], sv[3]);
#pragma unroll
            for (int c = 0; c < 4; c++) {
                if (i == bj + tx*4 + c) sv[c] = ninf();
                e[r][c] = sv[c];
                m = fmaxf(m, sv[c]);
            }
        }
        red[tid] = m; __syncthreads();
        for (int o = 128; o; o >>= 1) { if (tid < o) red[tid] = fmaxf(red[tid], red[tid+o]); __syncthreads(); }
        float M = red[0];
        __syncthreads();
        float se = 0.f;
#pragma unroll
        for (int r = 0; r < 4; r++)
#pragma unroll
            for (int c = 0; c < 4; c++) { float ev = expf(e[r][c] - M); e[r][c] = ev; se += ev; }
        red[tid] = se; __syncthreads();
        for (int o = 128; o; o >>= 1) { if (tid < o) red[tid] += red[tid+o]; __syncthreads(); }
        if (tid == 0) { p.mb[b] = M; p.seb[b] = red[0]; }

        u64 eh[4][2];
#pragma unroll
        for (int r = 0; r < 4; r++) {
            eh[r][0] = pk2x(e[r][0]*0.5f, e[r][1]*0.5f);
            eh[r][1] = pk2x(e[r][2]*0.5f, e[r][3]*0.5f);
        }
        for (int k0 = 0; k0 < DIM; k0 += 32) {
#pragma unroll
            for (int q = 0; q < 8; q++) {
                int t = tid + q * 256;
                int i = t >> 5, k = t & 31;
                sA[k][i] = p.Aa[(bi + i) * DIM + k0 + k];
                sB[k][i] = p.Bb[(bj + i) * DIM + k0 + k];
            }
            __syncthreads();
#pragma unroll
            for (int k = 0; k < 32; k++) {
                float4 av = *(float4*)&sA[k][ty*4];
                u64 A0 = pk2(av.x), A1 = pk2(av.y), A2 = pk2(av.z), A3 = pk2(av.w);
                u64 B01 = f2u(*(float2*)&sB[k][tx*4]);
                u64 B23 = f2u(*(float2*)&sB[k][tx*4 + 2]);
                u64 c0 = 0ULL, c1 = 0ULL, c2 = 0ULL, c3 = 0ULL;
                rfma2(c0, A0, B01, eh[0][0]); rfma2(c0, A0, B23, eh[0][1]);
                rfma2(c1, A1, B01, eh[1][0]); rfma2(c1, A1, B23, eh[1][1]);
                rfma2(c2, A2, B01, eh[2][0]); rfma2(c2, A2, B23, eh[2][1]);
                rfma2(c3, A3, B01, eh[3][0]); rfma2(c3, A3, B23, eh[3][1]);
                u64 s01 = add2(c0, c1), s23 = add2(c2, c3);
                float plo, phi; upk(add2(s01, s23), plo, phi);
                float pk = plo + phi;
#pragma unroll
                for (int o = 16; o; o >>= 1) pk += __shfl_down_sync(0xffffffffu, pk, o);
                if (lane == 0) gsh[k * 8 + warp] = pk;
            }
            __syncthreads();
            if (tid < 32) {
                float s8 = 0.f;
#pragma unroll
                for (int w2 = 0; w2 < 8; w2++) s8 += gsh[tid * 8 + w2];
                p.gpart[b * DIM + k0 + tid] = s8;
            }
            __syncthreads();
        }
    } else if (bid == 64) {
        // tf = sum of 4 partials, then H3 prefix-mean scan
        for (int idx = tid; idx < NVHD; idx += 256)
            p.tf[idx] = p.tfp[idx] + p.tfp[NVHD + idx] + p.tfp[2*NVHD + idx] + p.tfp[3*NVHD + idx];
        __syncthreads();
        float* cs = buf;
        int d = tid & 63, g = tid >> 6;
        float s0 = 0.f, s1 = 0.f, s2 = 0.f, s3 = 0.f;
        for (int r = 0; r < 32; r++) {
            s0 += p.tf[(32*(4*g+0)+r)*HD + d];
            s1 += p.tf[(32*(4*g+1)+r)*HD + d];
            s2 += p.tf[(32*(4*g+2)+r)*HD + d];
            s3 += p.tf[(32*(4*g+3)+r)*HD + d];
        }
        cs[(4*g+0)*64 + d] = s0; cs[(4*g+1)*64 + d] = s1;
        cs[(4*g+2)*64 + d] = s2; cs[(4*g+3)*64 + d] = s3;
        __syncthreads();
#pragma unroll
        for (int cc = 0; cc < 4; cc++) {
            int c = 4*g + cc;
            float run = 0.f;
            for (int c2 = 0; c2 < c; c2++) run += cs[c2*64 + d];
            for (int r = 0; r < 32; r++) {
                int row = 32*c + r;
                run += p.tf[row*HD + d];
                p.H3[row*HD + d] = run / (float)(row + 1);
            }
        }
    } else if (bid == 65) {
        int d = tid & 63, g = tid >> 6;
        float s = 0.f;
        for (int r = g; r < NV; r += 4) {
            int idx = r*HD + d;
            s += p.cfp[idx] + p.cfp[NVHD + idx] + p.cfp[2*NVHD + idx] + p.cfp[3*NVHD + idx];
        }
        buf[tid] = s; __syncthreads();
        if (tid < 64) p.h4[tid] = buf[tid] + buf[tid+64] + buf[tid+128] + buf[tid+192];
    } else if (bid < 194) {
        int q = bid - 66, ks = q >> 5, t = q & 31;
        float* out = (ks == 0) ? p.Np0 : (ks == 1) ? p.Np1 : (ks == 2) ? p.Np2 : p.Np3;
        gemm_core(LdAdjE{p.adj, p.E}, p.Wh1, nullptr, out, DIM, ks*128, ks*128+128, 0,
                  (t>>2)*64, (t&3)*64, buf);
    } else {
        int w = (bid - 194) * 8 + (tid >> 5);
        int lane = tid & 31;
        float pr = 0.f;
        for (int j = lane; j < NV; j += 32) pr += (float)p.adj[w*NV + j] * p.E[j];
#pragma unroll
        for (int o = 16; o; o >>= 1) pr += __shfl_xor_sync(0xffffffffu, pr, o);
        if (lane == 0) p.Dinv[w] = 1.f / pr;
    }
}

// ---------- Wave 5: [combiner first] + op = Hcat@Wf (K split 8), 257 CTAs ----------
struct W5P {
    const float *Np0, *Np1, *Np2, *Np3, *Dinv, *H3, *h4, *Wf;
    const float *mb, *seb, *gpart, *cew2, *ceb2, *bo;
    float* opp;
    float* bias2;
};
__global__ void __launch_bounds__(256) k_w5(W5P p) {
    __shared__ __align__(16) float buf[4352];
    int b = blockIdx.x, tid = threadIdx.x;
    if (b == 0) {
        float* sw = buf;
        float* red = buf + 64;
        float* ga = buf + 128;
        float* sH2 = buf + 384;
        __shared__ float sM, sInv;
        float mv = (tid < 64) ? p.mb[tid] : ninf();
        if (tid < 64) red[tid] = mv;
        __syncthreads();
        for (int o = 32; o; o >>= 1) { if (tid < o) red[tid] = fmaxf(red[tid], red[tid+o]); __syncthreads(); }
        if (tid == 0) sM = red[0];
        __syncthreads();
        float swv = 0.f;
        if (tid < 64) { swv = expf(mv - sM); sw[tid] = swv; red[tid] = p.seb[tid] * swv; }
        __syncthreads();
        for (int o = 32; o; o >>= 1) { if (tid < o) red[tid] += red[tid+o]; __syncthreads(); }
        if (tid == 0) sInv = 1.f / red[0];
        __syncthreads();
        float g = 0.f;
        for (int bb = 0; bb < 64; bb++) g += p.gpart[bb * DIM + tid] * sw[bb];
        ga[tid] = g * sInv;
        __syncthreads();
        if (tid < 64) {
            float s = 0.f;
            for (int k = 0; k < DIM; k++) s += ga[k] * p.cew2[k*HD + tid];
            sH2[tid] = s + p.ceb2[tid];
        }
        __syncthreads();
        float s = 0.f;
        for (int d = 0; d < HD; d++) s += sH2[d] * p.Wf[(256 + d)*DIM + tid];
        p.bias2[tid] = s + p.bo[tid];
    } else {
        int q0 = b - 1;
        int ks = q0 >> 5, t = q0 & 31;
        const int kb[8] = {0, 44, 88, 132, 176, 220, 320, 352};
        const int ke[8] = {44, 88, 132, 176, 220, 256, 352, 385};
        LdHcat ld{p.Np0, p.Np1, p.Np2, p.Np3, p.Dinv, p.H3, p.h4};
        gemm_core(ld, p.Wf, nullptr, p.opp + ks * (NV*DIM), DIM,
                  kb[ks], ke[ks], 0, (t>>2)*64, (t&3)*64, buf);
    }
}

// ---------- layernorm + elu ----------
struct LNP {
    const float* opp;
    const float *bias2, *g, *b;
    float* out;
};
__global__ void __launch_bounds__(256) k_lnelu(LNP p) {
    __shared__ float red[256];
    __shared__ float smu, svar;
    int i = blockIdx.x, t = threadIdx.x;
    int off = i*DIM + t;
    float x = p.bias2[t];
#pragma unroll
    for (int q = 0; q < 8; q++) x += p.opp[q * (NV*DIM) + off];
    red[t] = x; __syncthreads();
    for (int o = 128; o; o >>= 1) { if (t < o) red[t] += red[t+o]; __syncthreads(); }
    if (t == 0) smu = red[0] / (float)DIM;
    __syncthreads();
    float d = x - smu;
    red[t] = d * d; __syncthreads();
    for (int o = 128; o; o >>= 1) { if (t < o) red[t] += red[t+o]; __syncthreads(); }
    if (t == 0) svar = red[0] / (float)DIM;
    __syncthreads();
    float y = d * rsqrtf(svar + EPSLN) * p.g[t] + p.b[t];
    p.out[off] = (y > 0.f) ? y : expm1f(y);
}

extern "C" void kernel_launch(void* const* d_in, const int* in_sizes, int n_in,
                              void* d_out, int out_size) {
    const float* V      = (const float*)d_in[0];
    const int*   adj    = (const int*)d_in[1];
    const float* ph     = (const float*)d_in[2];
    const float* W1     = (const float*)d_in[3];
    const float* a_std1 = (const float*)d_in[5];
    const float* ce_w1  = (const float*)d_in[6];
    const float* ce_b1  = (const float*)d_in[7];
    const float* ce_w2  = (const float*)d_in[8];
    const float* ce_b2  = (const float*)d_in[9];
    const float* a_c0   = (const float*)d_in[10];
    const float* a_c1   = (const float*)d_in[11];
    const float* te_w1  = (const float*)d_in[12];
    const float* te_b1  = (const float*)d_in[13];
    const float* te_w2  = (const float*)d_in[14];
    const float* te_b2  = (const float*)d_in[15];
    const float* co_w1  = (const float*)d_in[18];
    const float* co_b1  = (const float*)d_in[19];
    const float* co_w2  = (const float*)d_in[20];
    const float* co_b2  = (const float*)d_in[21];
    const float* W2     = (const float*)d_in[24];
    const float* Wo     = (const float*)d_in[25];
    const float* bo     = (const float*)d_in[26];
    const float* ln_g   = (const float*)d_in[27];
    const float* ln_b   = (const float*)d_in[28];
    float* out = (float*)d_out;

    Scratch* s = nullptr;
    cudaGetSymbolAddress((void**)&s, g_s);

    W1P p1 = { V, ph, W1, ce_w1, ce_b1, te_w1, te_b1, te_w2, te_b2,
               co_w1, co_b1, co_w2, co_b2, ce_w2, a_c0, a_c1, W2, Wo, a_std1, adj,
               s->Wh1, s->Aa, s->Bb, s->wc, s->Wf, s->E, s->tfp[0], s->cfp[0] };
    k_w1<<<197, 256>>>(p1);

    W2P p2 = { s->Aa, s->Bb, s->wc, s->Wh1, s->E, s->tfp[0], s->cfp[0], adj,
               s->mb, s->seb, s->gpart, s->tf, s->H3, s->h4,
               s->Np0, s->Np1, s->Np2, s->Np3, s->Dinv };
    k_w2<<<258, 256>>>(p2);

    W5P p5 = { s->Np0, s->Np1, s->Np2, s->Np3, s->Dinv, s->H3, s->h4, s->Wf,
               s->mb, s->seb, s->gpart, ce_w2, ce_b2, bo,
               s->opp[0], s->bias2 };
    k_w5<<<257, 256>>>(p5);

    LNP pl = { s->opp[0], s->bias2, ln_g, ln_b, out };
    k_lnelu<<<NV, 256>>>(pl);
}

// round 16
// speedup vs baseline: 1.3369x; 1.3369x over previous
#include <cuda_runtime.h>
#include <math.h>
#include <string.h>

#define NV 512
#define DIM 256
#define HD 64
#define EPSLN 1e-5f
typedef unsigned long long u64;

struct Scratch {
    float Wh1[NV*DIM], Aa[NV*DIM], Bb[NV*DIM];
    float thp0[NV*DIM], thp1[NV*DIM];
    float chp0[NV*DIM], chp1[NV*DIM], chp2[NV*DIM];
    float tf[NV*HD], E[NV], U[NV*DIM], Dinv[NV];
    float Np0[NV*DIM], Np1[NV*DIM], Np2[NV*DIM], Np3[NV*DIM];
    float wc[DIM];
    float Sp[4][NV*NV];
    float mb[64], seb[64], gpart[64*DIM];
    float H3[NV*HD], cf4[NV*HD], h4[HD];
    float Wf[448*DIM];
    float bias2[DIM];
    float opp[8][NV*DIM];
};
__device__ Scratch g_s;

__device__ __forceinline__ float ninf() { return __int_as_float(0xff800000); }
__device__ __forceinline__ u64 pk2(float x) { u64 r; asm("mov.b64 %0,{%1,%1};":"=l"(r):"f"(x)); return r; }
__device__ __forceinline__ u64 pk2x(float a, float b) { u64 r; asm("mov.b64 %0,{%1,%2};":"=l"(r):"f"(a),"f"(b)); return r; }
__device__ __forceinline__ u64 f2u(float2 v) { u64 r; memcpy(&r, &v, 8); return r; }
__device__ __forceinline__ void upk(u64 v, float& lo, float& hi) { asm("mov.b64 {%0,%1},%2;":"=f"(lo),"=f"(hi):"l"(v)); }
__device__ __forceinline__ void fma2(u64& acc, u64 a, u64 b) { asm("fma.rn.f32x2 %0,%1,%2,%0;":"+l"(acc):"l"(a),"l"(b)); }
__device__ __forceinline__ u64 add2(u64 a, u64 b) { u64 r; asm("add.rn.f32x2 %0,%1,%2;":"=l"(r):"l"(a),"l"(b)); return r; }
__device__ __forceinline__ void rfma2(u64& acc, u64 a, u64 b, u64 wh) {
    u64 t = add2(a, b);
    u64 u = add2(t, t & 0x7FFFFFFF7FFFFFFFULL);
    asm("fma.rn.f32x2 %0,%1,%2,%0;":"+l"(acc):"l"(u),"l"(wh));
}

// ---------- loaders ----------
struct LdA { const float* A; int ld;
    __device__ __forceinline__ float operator()(int i, int k) const { return A[i*ld + k]; } };
struct LdW2g { const float* A;
    __device__ __forceinline__ float operator()(int i, int k) const {
        return (i < 385) ? A[i*DIM + k] : 0.f; } };
struct LdAdj { const int* a;
    __device__ __forceinline__ float operator()(int i, int k) const { return (float)a[i*NV + k]; } };
struct LdXt { const float *V, *ph;
    __device__ __forceinline__ float operator()(int i, int k) const {
        return (k < DIM) ? V[i*DIM + k] : ph[i*DIM + k - DIM]; } };
struct LdCi { const float* V; const int *n0, *n1, *va; int bi;
    __device__ __forceinline__ float operator()(int i, int k) const {
        if (k < DIM) return V[i*DIM + k];
        int r = i - bi;
        if (!va[r]) return 0.f;
        return (k < 2*DIM) ? V[n0[r]*DIM + k - DIM] : V[n1[r]*DIM + k - 2*DIM]; } };
struct LdRelu2 { const float *p0, *p1, *b;
    __device__ __forceinline__ float operator()(int i, int k) const {
        return fmaxf(p0[i*DIM+k] + p1[i*DIM+k] + b[k], 0.f); } };
struct LdRelu3 { const float *p0, *p1, *p2, *b;
    __device__ __forceinline__ float operator()(int i, int k) const {
        return fmaxf(p0[i*DIM+k] + p1[i*DIM+k] + p2[i*DIM+k] + b[k], 0.f); } };
struct LdHcat { const float *n0, *n1, *n2, *n3, *Di, *H3, *h4;
    __device__ __forceinline__ float operator()(int i, int c) const {
        if (c < 256) return (n0[i*DIM+c] + n1[i*DIM+c] + n2[i*DIM+c] + n3[i*DIM+c]) * Di[i];
        if (c < 384) return H3[i*HD + (c - 320)];
        return (i < HD) ? h4[i] : 0.f; } };

// ---------- 64x64 GEMM tile, packed FFMA2, double-buffered smem ----------
template <class FA>
__device__ __forceinline__ void gemm_core(const FA& loadA, const float* __restrict__ W,
                                          const float* __restrict__ bias, float* __restrict__ C,
                                          int Nn, int kbeg, int kend, int relu,
                                          int bi, int bj, float* buf) {
    float (*sA)[16][68] = (float(*)[16][68])buf;
    float (*sW)[16][68] = (float(*)[16][68])(buf + 2*16*68);
    int tid = threadIdx.x, tx = tid & 15, ty = tid >> 4;
    u64 a01c[4], a23c[4];
#pragma unroll
    for (int c = 0; c < 4; c++) { a01c[c] = 0ULL; a23c[c] = 0ULL; }

    int nIter = (kend - kbeg + 15) >> 4;
    float rA[4], rW[4];
#pragma unroll
    for (int p = 0; p < 4; p++) {
        int t = tid + p*256;
        int ia = t >> 4, ka = t & 15, kk = kbeg + ka;
        rA[p] = (kk < kend) ? loadA(bi + ia, kk) : 0.f;
        int kw = t >> 6, jw = t & 63, k2 = kbeg + kw;
        rW[p] = (k2 < kend) ? W[k2 * Nn + bj + jw] : 0.f;
    }
#pragma unroll
    for (int p = 0; p < 4; p++) {
        int t = tid + p*256;
        sA[0][t & 15][t >> 4] = rA[p];
        sW[0][t >> 6][t & 63] = rW[p];
    }
    __syncthreads();

    for (int it = 0; it < nIter; it++) {
        int cur = it & 1;
        if (it + 1 < nIter) {
            int k0n = kbeg + (it + 1) * 16;
#pragma unroll
            for (int p = 0; p < 4; p++) {
                int t = tid + p*256;
                int ia = t >> 4, ka = t & 15, kk = k0n + ka;
                rA[p] = (kk < kend) ? loadA(bi + ia, kk) : 0.f;
                int kw = t >> 6, jw = t & 63, k2 = k0n + kw;
                rW[p] = (k2 < kend) ? W[k2 * Nn + bj + jw] : 0.f;
            }
        }
#pragma unroll
        for (int k = 0; k < 16; k++) {
            float4 av = *(float4*)&sA[cur][k][ty*4];
            u64 a01 = pk2x(av.x, av.y);
            u64 a23 = pk2x(av.z, av.w);
            float4 wv = *(float4*)&sW[cur][k][tx*4];
            u64 b0 = pk2(wv.x), b1 = pk2(wv.y), b2 = pk2(wv.z), b3 = pk2(wv.w);
            fma2(a01c[0], a01, b0); fma2(a01c[1], a01, b1);
            fma2(a01c[2], a01, b2); fma2(a01c[3], a01, b3);
            fma2(a23c[0], a23, b0); fma2(a23c[1], a23, b1);
            fma2(a23c[2], a23, b2); fma2(a23c[3], a23, b3);
        }
        if (it + 1 < nIter) {
            int nxt = cur ^ 1;
#pragma unroll
            for (int p = 0; p < 4; p++) {
                int t = tid + p*256;
                sA[nxt][t & 15][t >> 4] = rA[p];
                sW[nxt][t >> 6][t & 63] = rW[p];
            }
            __syncthreads();
        }
    }
    float acc[4][4];
#pragma unroll
    for (int c = 0; c < 4; c++) {
        upk(a01c[c], acc[0][c], acc[1][c]);
        upk(a23c[c], acc[2][c], acc[3][c]);
    }
#pragma unroll
    for (int r = 0; r < 4; r++) {
        int i = bi + ty*4 + r;
#pragma unroll
        for (int c = 0; c < 4; c++) {
            int j = bj + tx*4 + c;
            float v = acc[r][c];
            if (bias) v += bias[j];
            if (relu) v = fmaxf(v, 0.f);
            C[i * Nn + j] = v;
        }
    }
}

// ---------- Wave 1: input GEMMs + wc + Wf + E, 293 CTAs ----------
struct W1P {
    const float *V, *ph, *W1, *cew1, *ceb1, *tew1, *cow1, *cew2, *ac0, *ac1, *W2, *Wo, *astd1;
    const int* adj;
    float *Wh1, *Aa, *Bb, *thp0, *thp1, *chp0, *chp1, *chp2, *wc, *Wf, *E;
};
__global__ void __launch_bounds__(256) k_w1(W1P p) {
    __shared__ __align__(16) float buf[4352];
    __shared__ int sn0[64], sn1[64], sva[64];
    __shared__ float sa[DIM];
    int b = blockIdx.x, tid = threadIdx.x;
    if (b < 32) {
        gemm_core(LdA{p.V, DIM}, p.W1, nullptr, p.Wh1, DIM, 0, DIM, 0, (b>>2)*64, (b&3)*64, buf);
    } else if (b < 64) {
        int q = b - 32;
        gemm_core(LdA{p.V, DIM}, p.cew1, p.ceb1, p.Aa, DIM, 0, DIM, 0, (q>>2)*64, (q&3)*64, buf);
    } else if (b < 96) {
        int q = b - 64;
        gemm_core(LdA{p.V, DIM}, p.cew1 + DIM*DIM, nullptr, p.Bb, DIM, 0, DIM, 0, (q>>2)*64, (q&3)*64, buf);
    } else if (b < 160) {
        int q = b - 96, half = q >> 5, t = q & 31;
        gemm_core(LdXt{p.V, p.ph}, p.tew1, nullptr, half ? p.thp1 : p.thp0, DIM,
                  half*256, half*256+256, 0, (t>>2)*64, (t&3)*64, buf);
    } else if (b < 256) {
        int q = b - 160, third = q >> 5, t = q & 31;
        int bi = (t >> 2) * 64;
        int warp = tid >> 5, lane = tid & 31;
#pragma unroll
        for (int rr = 0; rr < 8; rr++) {
            int r = warp*8 + rr, i = bi + r;
            int found = 0, a0 = 0, a1 = 0;
            for (int base = 0; base < NV && found < 2; base += 32) {
                int a = p.adj[i*NV + base + lane];
                unsigned m = __ballot_sync(0xffffffffu, a == 1);
                while (m && found < 2) {
                    int bb = __ffs(m) - 1;
                    if (!found) a0 = base + bb; else a1 = base + bb;
                    found++;
                    m &= m - 1;
                }
            }
            if (lane == 0) { sn0[r] = a0; sn1[r] = a1; sva[r] = (found == 2); }
        }
        __syncthreads();
        float* out = (third == 0) ? p.chp0 : (third == 1) ? p.chp1 : p.chp2;
        gemm_core(LdCi{p.V, sn0, sn1, sva, bi}, p.cow1, nullptr, out, DIM,
                  third*256, third*256+256, 0, bi, (t&3)*64, buf);
    } else if (b == 256) {
        if (tid < HD) sa[tid] = p.ac0[tid] + p.ac1[tid];
        __syncthreads();
        float s = 0.f;
        for (int d = 0; d < HD; d++) s += p.cew2[tid*HD + d] * sa[d];
        p.wc[tid] = s;
    } else if (b < 285) {
        int q = b - 257;
        gemm_core(LdW2g{p.W2}, p.Wo, nullptr, p.Wf, DIM, 0, DIM, 0, (q>>2)*64, (q&3)*64, buf);
    } else {
        // E = exp(V @ (W1 @ a_std1)); 8 CTAs x 64 rows (verified in R13/R15)
        int eb = b - 285;
        float s = 0.f;
        for (int j = 0; j < DIM; j++) s += p.W1[tid*DIM + j] * p.astd1[j];
        sa[tid] = s;
        __syncthreads();
        int warp = tid >> 5, lane = tid & 31;
#pragma unroll
        for (int rr = 0; rr < 8; rr++) {
            int w = eb*64 + warp*8 + rr;
            float pr = 0.f;
            for (int k = lane; k < DIM; k += 32) pr += p.V[w*DIM + k] * sa[k];
#pragma unroll
            for (int o = 16; o; o >>= 1) pr += __shfl_xor_sync(0xffffffffu, pr, o);
            if (lane == 0) p.E[w] = expf(pr);
        }
    }
}

// ---------- Wave 2: [tf cf4 U vecD first] + pair1(k/4), 344 CTAs ----------
struct W2P {
    const float *Aa, *Bb, *wc;
    const float *thp0, *thp1, *teb1, *tew2, *teb2;
    const float *chp0, *chp1, *chp2, *cob1, *cow2, *cob2;
    const float *Wh1, *E;
    const int* adj;
    float *Sp0, *Sp1, *Sp2, *Sp3, *tf, *cf4, *U, *Dinv;
};
__global__ void __launch_bounds__(256) k_w2(W2P p) {
    __shared__ __align__(16) float buf[4416];
    int bid = blockIdx.x, tid = threadIdx.x;
    if (bid < 8) {
        gemm_core(LdRelu2{p.thp0, p.thp1, p.teb1}, p.tew2, p.teb2, p.tf, HD,
                  0, DIM, 0, bid * 64, 0, buf);
    } else if (bid < 16) {
        gemm_core(LdRelu3{p.chp0, p.chp1, p.chp2, p.cob1}, p.cow2, p.cob2, p.cf4, HD,
                  0, DIM, 0, (bid - 8) * 64, 0, buf);
    } else if (bid < 24) {
        // U = E * Wh1 rows (E precomputed in w1)
        int base = (bid - 16) * 64;
        for (int idx = tid; idx < 64 * DIM; idx += 256) {
            int r = base + (idx >> 8);
            p.U[r*DIM + (idx & 255)] = p.E[r] * p.Wh1[r*DIM + (idx & 255)];
        }
    } else if (bid < 88) {
        int w = (bid - 24) * 8 + (tid >> 5);
        int lane = tid & 31;
        float pr = 0.f;
        for (int j = lane; j < NV; j += 32) pr += (float)p.adj[w*NV + j] * p.E[j];
#pragma unroll
        for (int o = 16; o; o >>= 1) pr += __shfl_xor_sync(0xffffffffu, pr, o);
        if (lane == 0) p.Dinv[w] = 1.f / pr;
    } else {
        float (*sA)[68] = (float(*)[68])buf;
        float (*sB)[68] = (float(*)[68])(buf + 32*68);
        float* swc = buf + 64*68;
        int q0 = bid - 88;
        int b = q0 >> 2, qk = q0 & 3;
        int bi = (b >> 3) * 64, bj = (b & 7) * 64;
        int kbeg = qk * 64;
        int tx = tid & 15, ty = tid >> 4;
        u64 acc[4][2];
#pragma unroll
        for (int r = 0; r < 4; r++) { acc[r][0] = 0ULL; acc[r][1] = 0ULL; }

        for (int k0 = kbeg; k0 < kbeg + 64; k0 += 32) {
#pragma unroll
            for (int q = 0; q < 8; q++) {
                int t = tid + q * 256;
                int i = t >> 5, k = t & 31;
                sA[k][i] = p.Aa[(bi + i) * DIM + k0 + k];
                sB[k][i] = p.Bb[(bj + i) * DIM + k0 + k];
            }
            if (tid < 32) swc[tid] = p.wc[k0 + tid] * 0.5f;
            __syncthreads();
#pragma unroll
            for (int k = 0; k < 32; k++) {
                u64 wh = pk2(swc[k]);
                float4 av = *(float4*)&sA[k][ty*4];
                u64 A0 = pk2(av.x), A1 = pk2(av.y), A2 = pk2(av.z), A3 = pk2(av.w);
                u64 B01 = f2u(*(float2*)&sB[k][tx*4]);
                u64 B23 = f2u(*(float2*)&sB[k][tx*4 + 2]);
                rfma2(acc[0][0], A0, B01, wh); rfma2(acc[0][1], A0, B23, wh);
                rfma2(acc[1][0], A1, B01, wh); rfma2(acc[1][1], A1, B23, wh);
                rfma2(acc[2][0], A2, B01, wh); rfma2(acc[2][1], A2, B23, wh);
                rfma2(acc[3][0], A3, B01, wh); rfma2(acc[3][1], A3, B23, wh);
            }
            __syncthreads();
        }
        float* Sp = (qk == 0) ? p.Sp0 : (qk == 1) ? p.Sp1 : (qk == 2) ? p.Sp2 : p.Sp3;
#pragma unroll
        for (int r = 0; r < 4; r++) {
            float l0, h0, l1, h1;
            upk(acc[r][0], l0, h0); upk(acc[r][1], l1, h1);
            *(float4*)&Sp[(bi + ty*4 + r) * NV + bj + tx*4] = make_float4(l0, h0, l1, h1);
        }
    }
}

// ---------- Wave 3: [H3 h4 Np first] + pair2(k/4), 386 CTAs ----------
struct W3P {
    const float *Aa, *Bb, *Sp0, *Sp1, *Sp2, *Sp3, *U, *tf, *cf4;
    const int* adj;
    float *mb, *seb, *gpart, *Np0, *Np1, *Np2, *Np3, *H3, *h4;
};
__global__ void __launch_bounds__(256) k_w3(W3P p) {
    __shared__ __align__(16) float buf[5120];
    int bid = blockIdx.x, tid = threadIdx.x;
    if (bid == 0) {
        float* cs = buf;
        int d = tid & 63, g = tid >> 6;
        float s0 = 0.f, s1 = 0.f, s2 = 0.f, s3 = 0.f;
        for (int r = 0; r < 32; r++) {
            s0 += p.tf[(32*(4*g+0)+r)*HD + d];
            s1 += p.tf[(32*(4*g+1)+r)*HD + d];
            s2 += p.tf[(32*(4*g+2)+r)*HD + d];
            s3 += p.tf[(32*(4*g+3)+r)*HD + d];
        }
        cs[(4*g+0)*64 + d] = s0; cs[(4*g+1)*64 + d] = s1;
        cs[(4*g+2)*64 + d] = s2; cs[(4*g+3)*64 + d] = s3;
        __syncthreads();
#pragma unroll
        for (int cc = 0; cc < 4; cc++) {
            int c = 4*g + cc;
            float run = 0.f;
            for (int c2 = 0; c2 < c; c2++) run += cs[c2*64 + d];
            for (int r = 0; r < 32; r++) {
                int row = 32*c + r;
                run += p.tf[row*HD + d];
                p.H3[row*HD + d] = run / (float)(row + 1);
            }
        }
    } else if (bid == 1) {
        int d = tid & 63, g = tid >> 6;
        float s = 0.f;
        for (int r = g; r < NV; r += 4) s += p.cf4[r*HD + d];
        buf[tid] = s; __syncthreads();
        if (tid < 64) p.h4[tid] = buf[tid] + buf[tid+64] + buf[tid+128] + buf[tid+192];
    } else if (bid < 130) {
        int q = bid - 2, ks = q >> 5, t = q & 31;
        float* out = (ks == 0) ? p.Np0 : (ks == 1) ? p.Np1 : (ks == 2) ? p.Np2 : p.Np3;
        gemm_core(LdAdj{p.adj}, p.U, nullptr, out, DIM, ks*128, ks*128+128, 0,
                  (t>>2)*64, (t&3)*64, buf);
    } else {
        float (*sA)[68] = (float(*)[68])buf;
        float (*sB)[68] = (float(*)[68])(buf + 32*68);
        float* red = buf + 64*68;
        float* gsh = red + 256;
        int q0 = bid - 130;
        int b = q0 >> 2, qk = q0 & 3;
        int bi = (b >> 3) * 64, bj = (b & 7) * 64;
        int kbeg = qk * 64;
        int tx = tid & 15, ty = tid >> 4;
        int warp = tid >> 5, lane = tid & 31;

        float e[4][4];
        float m = ninf();
#pragma unroll
        for (int r = 0; r < 4; r++) {
            int i = bi + ty*4 + r;
            float4 s0 = *(const float4*)&p.Sp0[i*NV + bj + tx*4];
            float4 s1 = *(const float4*)&p.Sp1[i*NV + bj + tx*4];
            float4 s2 = *(const float4*)&p.Sp2[i*NV + bj + tx*4];
            float4 s3 = *(const float4*)&p.Sp3[i*NV + bj + tx*4];
            float sv[4] = { (s0.x+s1.x)+(s2.x+s3.x), (s0.y+s1.y)+(s2.y+s3.y),
                            (s0.z+s1.z)+(s2.z+s3.z), (s0.w+s1.w)+(s2.w+s3.w) };
#pragma unroll
            for (int c = 0; c < 4; c++) {
                if (i == bj + tx*4 + c) sv[c] = ninf();
                e[r][c] = sv[c];
                m = fmaxf(m, sv[c]);
            }
        }
        red[tid] = m; __syncthreads();
        for (int o = 128; o; o >>= 1) { if (tid < o) red[tid] = fmaxf(red[tid], red[tid+o]); __syncthreads(); }
        float M = red[0];
        __syncthreads();
        float se = 0.f;
#pragma unroll
        for (int r = 0; r < 4; r++)
#pragma unroll
            for (int c = 0; c < 4; c++) { float ev = expf(e[r][c] - M); e[r][c] = ev; se += ev; }
        red[tid] = se; __syncthreads();
        for (int o = 128; o; o >>= 1) { if (tid < o) red[tid] += red[tid+o]; __syncthreads(); }
        if (qk == 0 && tid == 0) { p.mb[b] = M; p.seb[b] = red[0]; }

        u64 eh[4][2];
#pragma unroll
        for (int r = 0; r < 4; r++) {
            eh[r][0] = pk2x(e[r][0]*0.5f, e[r][1]*0.5f);
            eh[r][1] = pk2x(e[r][2]*0.5f, e[r][3]*0.5f);
        }
        for (int k0 = kbeg; k0 < kbeg + 64; k0 += 32) {
#pragma unroll
            for (int q = 0; q < 8; q++) {
                int t = tid + q * 256;
                int i = t >> 5, k = t & 31;
                sA[k][i] = p.Aa[(bi + i) * DIM + k0 + k];
                sB[k][i] = p.Bb[(bj + i) * DIM + k0 + k];
            }
            __syncthreads();
#pragma unroll
            for (int k = 0; k < 32; k++) {
                float4 av = *(float4*)&sA[k][ty*4];
                u64 A0 = pk2(av.x), A1 = pk2(av.y), A2 = pk2(av.z), A3 = pk2(av.w);
                u64 B01 = f2u(*(float2*)&sB[k][tx*4]);
                u64 B23 = f2u(*(float2*)&sB[k][tx*4 + 2]);
                u64 c0 = 0ULL, c1 = 0ULL, c2 = 0ULL, c3 = 0ULL;
                rfma2(c0, A0, B01, eh[0][0]); rfma2(c0, A0, B23, eh[0][1]);
                rfma2(c1, A1, B01, eh[1][0]); rfma2(c1, A1, B23, eh[1][1]);
                rfma2(c2, A2, B01, eh[2][0]); rfma2(c2, A2, B23, eh[2][1]);
                rfma2(c3, A3, B01, eh[3][0]); rfma2(c3, A3, B23, eh[3][1]);
                u64 s01 = add2(c0, c1), s23 = add2(c2, c3);
                float plo, phi; upk(add2(s01, s23), plo, phi);
                float pk = plo + phi;
#pragma unroll
                for (int o = 16; o; o >>= 1) pk += __shfl_down_sync(0xffffffffu, pk, o);
                if (lane == 0) gsh[(k0 - kbeg + k) * 8 + warp] = pk;
            }
            __syncthreads();
        }
        if (tid < 64) {
            float s8 = 0.f;
#pragma unroll
            for (int w2 = 0; w2 < 8; w2++) s8 += gsh[tid * 8 + w2];
            p.gpart[b * DIM + kbeg + tid] = s8;
        }
    }
}

// ---------- Wave 5: [combiner first] + op = Hcat@Wf (K split 8), 257 CTAs ----------
struct W5P {
    const float *Np0, *Np1, *Np2, *Np3, *Dinv, *H3, *h4, *Wf;
    const float *mb, *seb, *gpart, *cew2, *ceb2, *bo;
    float* opp;
    float* bias2;
};
__global__ void __launch_bounds__(256) k_w5(W5P p) {
    __shared__ __align__(16) float buf[4352];
    int b = blockIdx.x, tid = threadIdx.x;
    if (b == 0) {
        float* sw = buf;
        float* red = buf + 64;
        float* ga = buf + 128;
        float* sH2 = buf + 384;
        __shared__ float sM, sInv;
        float mv = (tid < 64) ? p.mb[tid] : ninf();
        if (tid < 64) red[tid] = mv;
        __syncthreads();
        for (int o = 32; o; o >>= 1) { if (tid < o) red[tid] = fmaxf(red[tid], red[tid+o]); __syncthreads(); }
        if (tid == 0) sM = red[0];
        __syncthreads();
        float swv = 0.f;
        if (tid < 64) { swv = expf(mv - sM); sw[tid] = swv; red[tid] = p.seb[tid] * swv; }
        __syncthreads();
        for (int o = 32; o; o >>= 1) { if (tid < o) red[tid] += red[tid+o]; __syncthreads(); }
        if (tid == 0) sInv = 1.f / red[0];
        __syncthreads();
        float g = 0.f;
        for (int bb = 0; bb < 64; bb++) g += p.gpart[bb * DIM + tid] * sw[bb];
        ga[tid] = g * sInv;
        __syncthreads();
        if (tid < 64) {
            float s = 0.f;
            for (int k = 0; k < DIM; k++) s += ga[k] * p.cew2[k*HD + tid];
            sH2[tid] = s + p.ceb2[tid];
        }
        __syncthreads();
        float s = 0.f;
        for (int d = 0; d < HD; d++) s += sH2[d] * p.Wf[(256 + d)*DIM + tid];
        p.bias2[tid] = s + p.bo[tid];
    } else {
        int q0 = b - 1;
        int ks = q0 >> 5, t = q0 & 31;
        const int kb[8] = {0, 44, 88, 132, 176, 220, 320, 352};
        const int ke[8] = {44, 88, 132, 176, 220, 256, 352, 385};
        LdHcat ld{p.Np0, p.Np1, p.Np2, p.Np3, p.Dinv, p.H3, p.h4};
        gemm_core(ld, p.Wf, nullptr, p.opp + ks * (NV*DIM), DIM,
                  kb[ks], ke[ks], 0, (t>>2)*64, (t&3)*64, buf);
    }
}

// ---------- layernorm + elu ----------
struct LNP {
    const float* opp;
    const float *bias2, *g, *b;
    float* out;
};
__global__ void __launch_bounds__(256) k_lnelu(LNP p) {
    __shared__ float red[256];
    __shared__ float smu, svar;
    int i = blockIdx.x, t = threadIdx.x;
    int off = i*DIM + t;
    float x = p.bias2[t];
#pragma unroll
    for (int q = 0; q < 8; q++) x += p.opp[q * (NV*DIM) + off];
    red[t] = x; __syncthreads();
    for (int o = 128; o; o >>= 1) { if (t < o) red[t] += red[t+o]; __syncthreads(); }
    if (t == 0) smu = red[0] / (float)DIM;
    __syncthreads();
    float d = x - smu;
    red[t] = d * d; __syncthreads();
    for (int o = 128; o; o >>= 1) { if (t < o) red[t] += red[t+o]; __syncthreads(); }
    if (t == 0) svar = red[0] / (float)DIM;
    __syncthreads();
    float y = d * rsqrtf(svar + EPSLN) * p.g[t] + p.b[t];
    p.out[off] = (y > 0.f) ? y : expm1f(y);
}

extern "C" void kernel_launch(void* const* d_in, const int* in_sizes, int n_in,
                              void* d_out, int out_size) {
    const float* V      = (const float*)d_in[0];
    const int*   adj    = (const int*)d_in[1];
    const float* ph     = (const float*)d_in[2];
    const float* W1     = (const float*)d_in[3];
    const float* a_std1 = (const float*)d_in[5];
    const float* ce_w1  = (const float*)d_in[6];
    const float* ce_b1  = (const float*)d_in[7];
    const float* ce_w2  = (const float*)d_in[8];
    const float* ce_b2  = (const float*)d_in[9];
    const float* a_c0   = (const float*)d_in[10];
    const float* a_c1   = (const float*)d_in[11];
    const float* te_w1  = (const float*)d_in[12];
    const float* te_b1  = (const float*)d_in[13];
    const float* te_w2  = (const float*)d_in[14];
    const float* te_b2  = (const float*)d_in[15];
    const float* co_w1  = (const float*)d_in[18];
    const float* co_b1  = (const float*)d_in[19];
    const float* co_w2  = (const float*)d_in[20];
    const float* co_b2  = (const float*)d_in[21];
    const float* W2     = (const float*)d_in[24];
    const float* Wo     = (const float*)d_in[25];
    const float* bo     = (const float*)d_in[26];
    const float* ln_g   = (const float*)d_in[27];
    const float* ln_b   = (const float*)d_in[28];
    float* out = (float*)d_out;

    Scratch* s = nullptr;
    cudaGetSymbolAddress((void**)&s, g_s);

    W1P p1 = { V, ph, W1, ce_w1, ce_b1, te_w1, co_w1, ce_w2, a_c0, a_c1, W2, Wo, a_std1, adj,
               s->Wh1, s->Aa, s->Bb, s->thp0, s->thp1, s->chp0, s->chp1, s->chp2, s->wc, s->Wf, s->E };
    k_w1<<<293, 256>>>(p1);

    W2P p2 = { s->Aa, s->Bb, s->wc,
               s->thp0, s->thp1, te_b1, te_w2, te_b2,
               s->chp0, s->chp1, s->chp2, co_b1, co_w2, co_b2,
               s->Wh1, s->E, adj,
               s->Sp[0], s->Sp[1], s->Sp[2], s->Sp[3], s->tf, s->cf4, s->U, s->Dinv };
    k_w2<<<344, 256>>>(p2);

    W3P p3 = { s->Aa, s->Bb, s->Sp[0], s->Sp[1], s->Sp[2], s->Sp[3], s->U, s->tf, s->cf4, adj,
               s->mb, s->seb, s->gpart, s->Np0, s->Np1, s->Np2, s->Np3,
               s->H3, s->h4 };
    k_w3<<<386, 256>>>(p3);

    W5P p5 = { s->Np0, s->Np1, s->Np2, s->Np3, s->Dinv, s->H3, s->h4, s->Wf,
               s->mb, s->seb, s->gpart, ce_w2, ce_b2, bo,
               s->opp[0], s->bias2 };
    k_w5<<<257, 256>>>(p5);

    LNP pl = { s->opp[0], s->bias2, ln_g, ln_b, out };
    k_lnelu<<<NV, 256>>>(pl);
}

// round 17
// speedup vs baseline: 1.6077x; 1.2026x over previous
#include <cuda_runtime.h>
#include <math.h>
#include <string.h>

#define NV 512
#define DIM 256
#define HD 64
#define EPSLN 1e-5f
typedef unsigned long long u64;

struct Scratch {
    float Wh1[NV*DIM], Aa[NV*DIM], Bb[NV*DIM];
    float thp0[NV*DIM], thp1[NV*DIM];
    float chp0[NV*DIM], chp1[NV*DIM], chp2[NV*DIM];
    float tf[NV*HD], E[NV], U[NV*DIM], Dinv[NV];
    float Np0[NV*DIM], Np1[NV*DIM], Np2[NV*DIM], Np3[NV*DIM];
    float wc[DIM];
    float Sp[4][NV*NV];
    float mb[64], seb[64], gpart[64*DIM];
    float H3[NV*HD], cf4[NV*HD], h4[HD];
    float Wf[448*DIM];
    float bias2[DIM];
    float opp[8][NV*DIM];
};
__device__ Scratch g_s;

__device__ __forceinline__ float ninf() { return __int_as_float(0xff800000); }
__device__ __forceinline__ u64 pk2(float x) { u64 r; asm("mov.b64 %0,{%1,%1};":"=l"(r):"f"(x)); return r; }
__device__ __forceinline__ u64 pk2x(float a, float b) { u64 r; asm("mov.b64 %0,{%1,%2};":"=l"(r):"f"(a),"f"(b)); return r; }
__device__ __forceinline__ u64 f2u(float2 v) { u64 r; memcpy(&r, &v, 8); return r; }
__device__ __forceinline__ void upk(u64 v, float& lo, float& hi) { asm("mov.b64 {%0,%1},%2;":"=f"(lo),"=f"(hi):"l"(v)); }
__device__ __forceinline__ void fma2(u64& acc, u64 a, u64 b) { asm("fma.rn.f32x2 %0,%1,%2,%0;":"+l"(acc):"l"(a),"l"(b)); }
__device__ __forceinline__ u64 add2(u64 a, u64 b) { u64 r; asm("add.rn.f32x2 %0,%1,%2;":"=l"(r):"l"(a),"l"(b)); return r; }
__device__ __forceinline__ void rfma2(u64& acc, u64 a, u64 b, u64 wh) {
    u64 t = add2(a, b);
    u64 u = add2(t, t & 0x7FFFFFFF7FFFFFFFULL);
    asm("fma.rn.f32x2 %0,%1,%2,%0;":"+l"(acc):"l"(u),"l"(wh));
}

// ---------- loaders ----------
struct LdA { const float* A; int ld;
    __device__ __forceinline__ float operator()(int i, int k) const { return A[i*ld + k]; } };
struct LdW2g { const float* A;
    __device__ __forceinline__ float operator()(int i, int k) const {
        return (i < 385) ? A[i*DIM + k] : 0.f; } };
struct LdAdj { const int* a;
    __device__ __forceinline__ float operator()(int i, int k) const { return (float)a[i*NV + k]; } };
struct LdXt { const float *V, *ph;
    __device__ __forceinline__ float operator()(int i, int k) const {
        return (k < DIM) ? V[i*DIM + k] : ph[i*DIM + k - DIM]; } };
struct LdCi { const float* V; const int *n0, *n1, *va; int bi;
    __device__ __forceinline__ float operator()(int i, int k) const {
        if (k < DIM) return V[i*DIM + k];
        int r = i - bi;
        if (!va[r]) return 0.f;
        return (k < 2*DIM) ? V[n0[r]*DIM + k - DIM] : V[n1[r]*DIM + k - 2*DIM]; } };
struct LdRelu2 { const float *p0, *p1, *b;
    __device__ __forceinline__ float operator()(int i, int k) const {
        return fmaxf(p0[i*DIM+k] + p1[i*DIM+k] + b[k], 0.f); } };
struct LdRelu3 { const float *p0, *p1, *p2, *b;
    __device__ __forceinline__ float operator()(int i, int k) const {
        return fmaxf(p0[i*DIM+k] + p1[i*DIM+k] + p2[i*DIM+k] + b[k], 0.f); } };
struct LdHcat { const float *n0, *n1, *n2, *n3, *Di, *H3, *h4;
    __device__ __forceinline__ float operator()(int i, int c) const {
        if (c < 256) return (n0[i*DIM+c] + n1[i*DIM+c] + n2[i*DIM+c] + n3[i*DIM+c]) * Di[i];
        if (c < 384) return H3[i*HD + (c - 320)];
        return (i < HD) ? h4[i] : 0.f; } };

// ---------- 64x64 GEMM tile, packed FFMA2, double-buffered smem ----------
template <class FA>
__device__ __forceinline__ void gemm_core(const FA& loadA, const float* __restrict__ W,
                                          const float* __restrict__ bias, float* __restrict__ C,
                                          int Nn, int kbeg, int kend, int relu,
                                          int bi, int bj, float* buf) {
    float (*sA)[16][68] = (float(*)[16][68])buf;
    float (*sW)[16][68] = (float(*)[16][68])(buf + 2*16*68);
    int tid = threadIdx.x, tx = tid & 15, ty = tid >> 4;
    u64 a01c[4], a23c[4];
#pragma unroll
    for (int c = 0; c < 4; c++) { a01c[c] = 0ULL; a23c[c] = 0ULL; }

    int nIter = (kend - kbeg + 15) >> 4;
    float rA[4], rW[4];
#pragma unroll
    for (int p = 0; p < 4; p++) {
        int t = tid + p*256;
        int ia = t >> 4, ka = t & 15, kk = kbeg + ka;
        rA[p] = (kk < kend) ? loadA(bi + ia, kk) : 0.f;
        int kw = t >> 6, jw = t & 63, k2 = kbeg + kw;
        rW[p] = (k2 < kend) ? W[k2 * Nn + bj + jw] : 0.f;
    }
#pragma unroll
    for (int p = 0; p < 4; p++) {
        int t = tid + p*256;
        sA[0][t & 15][t >> 4] = rA[p];
        sW[0][t >> 6][t & 63] = rW[p];
    }
    __syncthreads();

    for (int it = 0; it < nIter; it++) {
        int cur = it & 1;
        if (it + 1 < nIter) {
            int k0n = kbeg + (it + 1) * 16;
#pragma unroll
            for (int p = 0; p < 4; p++) {
                int t = tid + p*256;
                int ia = t >> 4, ka = t & 15, kk = k0n + ka;
                rA[p] = (kk < kend) ? loadA(bi + ia, kk) : 0.f;
                int kw = t >> 6, jw = t & 63, k2 = k0n + kw;
                rW[p] = (k2 < kend) ? W[k2 * Nn + bj + jw] : 0.f;
            }
        }
#pragma unroll
        for (int k = 0; k < 16; k++) {
            float4 av = *(float4*)&sA[cur][k][ty*4];
            u64 a01 = pk2x(av.x, av.y);
            u64 a23 = pk2x(av.z, av.w);
            float4 wv = *(float4*)&sW[cur][k][tx*4];
            u64 b0 = pk2(wv.x), b1 = pk2(wv.y), b2 = pk2(wv.z), b3 = pk2(wv.w);
            fma2(a01c[0], a01, b0); fma2(a01c[1], a01, b1);
            fma2(a01c[2], a01, b2); fma2(a01c[3], a01, b3);
            fma2(a23c[0], a23, b0); fma2(a23c[1], a23, b1);
            fma2(a23c[2], a23, b2); fma2(a23c[3], a23, b3);
        }
        if (it + 1 < nIter) {
            int nxt = cur ^ 1;
#pragma unroll
            for (int p = 0; p < 4; p++) {
                int t = tid + p*256;
                sA[nxt][t & 15][t >> 4] = rA[p];
                sW[nxt][t >> 6][t & 63] = rW[p];
            }
            __syncthreads();
        }
    }
    float acc[4][4];
#pragma unroll
    for (int c = 0; c < 4; c++) {
        upk(a01c[c], acc[0][c], acc[1][c]);
        upk(a23c[c], acc[2][c], acc[3][c]);
    }
#pragma unroll
    for (int r = 0; r < 4; r++) {
        int i = bi + ty*4 + r;
#pragma unroll
        for (int c = 0; c < 4; c++) {
            int j = bj + tx*4 + c;
            float v = acc[r][c];
            if (bias) v += bias[j];
            if (relu) v = fmaxf(v, 0.f);
            C[i * Nn + j] = v;
        }
    }
}

// ---------- Wave 1: input GEMMs + wc + Wf, 285 CTAs ----------
struct W1P {
    const float *V, *ph, *W1, *cew1, *ceb1, *tew1, *cow1, *cew2, *ac0, *ac1, *W2, *Wo;
    const int* adj;
    float *Wh1, *Aa, *Bb, *thp0, *thp1, *chp0, *chp1, *chp2, *wc, *Wf;
};
__global__ void __launch_bounds__(256) k_w1(W1P p) {
    __shared__ __align__(16) float buf[4352];
    __shared__ int sn0[64], sn1[64], sva[64];
    __shared__ float sa[HD];
    int b = blockIdx.x, tid = threadIdx.x;
    if (b < 32) {
        gemm_core(LdA{p.V, DIM}, p.W1, nullptr, p.Wh1, DIM, 0, DIM, 0, (b>>2)*64, (b&3)*64, buf);
    } else if (b < 64) {
        int q = b - 32;
        gemm_core(LdA{p.V, DIM}, p.cew1, p.ceb1, p.Aa, DIM, 0, DIM, 0, (q>>2)*64, (q&3)*64, buf);
    } else if (b < 96) {
        int q = b - 64;
        gemm_core(LdA{p.V, DIM}, p.cew1 + DIM*DIM, nullptr, p.Bb, DIM, 0, DIM, 0, (q>>2)*64, (q&3)*64, buf);
    } else if (b < 160) {
        int q = b - 96, half = q >> 5, t = q & 31;
        gemm_core(LdXt{p.V, p.ph}, p.tew1, nullptr, half ? p.thp1 : p.thp0, DIM,
                  half*256, half*256+256, 0, (t>>2)*64, (t&3)*64, buf);
    } else if (b < 256) {
        int q = b - 160, third = q >> 5, t = q & 31;
        int bi = (t >> 2) * 64;
        int warp = tid >> 5, lane = tid & 31;
#pragma unroll
        for (int rr = 0; rr < 8; rr++) {
            int r = warp*8 + rr, i = bi + r;
            int found = 0, a0 = 0, a1 = 0;
            for (int base = 0; base < NV && found < 2; base += 32) {
                int a = p.adj[i*NV + base + lane];
                unsigned m = __ballot_sync(0xffffffffu, a == 1);
                while (m && found < 2) {
                    int bb = __ffs(m) - 1;
                    if (!found) a0 = base + bb; else a1 = base + bb;
                    found++;
                    m &= m - 1;
                }
            }
            if (lane == 0) { sn0[r] = a0; sn1[r] = a1; sva[r] = (found == 2); }
        }
        __syncthreads();
        float* out = (third == 0) ? p.chp0 : (third == 1) ? p.chp1 : p.chp2;
        gemm_core(LdCi{p.V, sn0, sn1, sva, bi}, p.cow1, nullptr, out, DIM,
                  third*256, third*256+256, 0, bi, (t&3)*64, buf);
    } else if (b == 256) {
        if (tid < HD) sa[tid] = p.ac0[tid] + p.ac1[tid];
        __syncthreads();
        float s = 0.f;
        for (int d = 0; d < HD; d++) s += p.cew2[tid*HD + d] * sa[d];
        p.wc[tid] = s;
    } else {
        int q = b - 257;
        gemm_core(LdW2g{p.W2}, p.Wo, nullptr, p.Wf, DIM, 0, DIM, 0, (q>>2)*64, (q&3)*64, buf);
    }
}

// ---------- Wave 2: [tf cf4 vecE first] + pair1(k/4), 280 CTAs ----------
struct W2P {
    const float *Aa, *Bb, *wc;
    const float *thp0, *thp1, *teb1, *tew2, *teb2;
    const float *chp0, *chp1, *chp2, *cob1, *cow2, *cob2;
    const float *Wh1, *astd1;
    float *Sp0, *Sp1, *Sp2, *Sp3, *tf, *cf4, *E, *U;
};
__global__ void __launch_bounds__(256) k_w2(W2P p) {
    __shared__ __align__(16) float buf[4416];
    int bid = blockIdx.x, tid = threadIdx.x;
    if (bid < 8) {
        gemm_core(LdRelu2{p.thp0, p.thp1, p.teb1}, p.tew2, p.teb2, p.tf, HD,
                  0, DIM, 0, bid * 64, 0, buf);
    } else if (bid < 16) {
        gemm_core(LdRelu3{p.chp0, p.chp1, p.chp2, p.cob1}, p.cow2, p.cob2, p.cf4, HD,
                  0, DIM, 0, (bid - 8) * 64, 0, buf);
    } else if (bid < 24) {
        int warp = tid >> 5, lane = tid & 31;
#pragma unroll
        for (int rr = 0; rr < 8; rr++) {
            int w = (bid - 16) * 64 + warp*8 + rr;
            float pr = 0.f;
            for (int k = lane; k < DIM; k += 32) pr += p.Wh1[w*DIM + k] * p.astd1[k];
#pragma unroll
            for (int o = 16; o; o >>= 1) pr += __shfl_xor_sync(0xffffffffu, pr, o);
            float ev = expf(pr);
            if (lane == 0) p.E[w] = ev;
            for (int k = lane; k < DIM; k += 32) p.U[w*DIM + k] = ev * p.Wh1[w*DIM + k];
        }
    } else {
        float (*sA)[68] = (float(*)[68])buf;
        float (*sB)[68] = (float(*)[68])(buf + 32*68);
        float* swc = buf + 64*68;
        int q0 = bid - 24;
        int b = q0 >> 2, qk = q0 & 3;
        int bi = (b >> 3) * 64, bj = (b & 7) * 64;
        int kbeg = qk * 64;
        int tx = tid & 15, ty = tid >> 4;
        u64 acc[4][2];
#pragma unroll
        for (int r = 0; r < 4; r++) { acc[r][0] = 0ULL; acc[r][1] = 0ULL; }

        for (int k0 = kbeg; k0 < kbeg + 64; k0 += 32) {
#pragma unroll
            for (int q = 0; q < 8; q++) {
                int t = tid + q * 256;
                int i = t >> 5, k = t & 31;
                sA[k][i] = p.Aa[(bi + i) * DIM + k0 + k];
                sB[k][i] = p.Bb[(bj + i) * DIM + k0 + k];
            }
            if (tid < 32) swc[tid] = p.wc[k0 + tid] * 0.5f;
            __syncthreads();
#pragma unroll
            for (int k = 0; k < 32; k++) {
                u64 wh = pk2(swc[k]);
                float4 av = *(float4*)&sA[k][ty*4];
                u64 A0 = pk2(av.x), A1 = pk2(av.y), A2 = pk2(av.z), A3 = pk2(av.w);
                u64 B01 = f2u(*(float2*)&sB[k][tx*4]);
                u64 B23 = f2u(*(float2*)&sB[k][tx*4 + 2]);
                rfma2(acc[0][0], A0, B01, wh); rfma2(acc[0][1], A0, B23, wh);
                rfma2(acc[1][0], A1, B01, wh); rfma2(acc[1][1], A1, B23, wh);
                rfma2(acc[2][0], A2, B01, wh); rfma2(acc[2][1], A2, B23, wh);
                rfma2(acc[3][0], A3, B01, wh); rfma2(acc[3][1], A3, B23, wh);
            }
            __syncthreads();
        }
        float* Sp = (qk == 0) ? p.Sp0 : (qk == 1) ? p.Sp1 : (qk == 2) ? p.Sp2 : p.Sp3;
#pragma unroll
        for (int r = 0; r < 4; r++) {
            float l0, h0, l1, h1;
            upk(acc[r][0], l0, h0); upk(acc[r][1], l1, h1);
            *(float4*)&Sp[(bi + ty*4 + r) * NV + bj + tx*4] = make_float4(l0, h0, l1, h1);
        }
    }
}

// ---------- Wave 3: [H3 h4 Np vecD first] + pair2(k/4), 450 CTAs ----------
struct W3P {
    const float *Aa, *Bb, *Sp0, *Sp1, *Sp2, *Sp3, *U, *E, *tf, *cf4;
    const int* adj;
    float *mb, *seb, *gpart, *Np0, *Np1, *Np2, *Np3, *Dinv, *H3, *h4;
};
__global__ void __launch_bounds__(256) k_w3(W3P p) {
    __shared__ __align__(16) float buf[5120];
    int bid = blockIdx.x, tid = threadIdx.x;
    if (bid == 0) {
        float* cs = buf;
        int d = tid & 63, g = tid >> 6;
        float s0 = 0.f, s1 = 0.f, s2 = 0.f, s3 = 0.f;
        for (int r = 0; r < 32; r++) {
            s0 += p.tf[(32*(4*g+0)+r)*HD + d];
            s1 += p.tf[(32*(4*g+1)+r)*HD + d];
            s2 += p.tf[(32*(4*g+2)+r)*HD + d];
            s3 += p.tf[(32*(4*g+3)+r)*HD + d];
        }
        cs[(4*g+0)*64 + d] = s0; cs[(4*g+1)*64 + d] = s1;
        cs[(4*g+2)*64 + d] = s2; cs[(4*g+3)*64 + d] = s3;
        __syncthreads();
#pragma unroll
        for (int cc = 0; cc < 4; cc++) {
            int c = 4*g + cc;
            float run = 0.f;
            for (int c2 = 0; c2 < c; c2++) run += cs[c2*64 + d];
            for (int r = 0; r < 32; r++) {
                int row = 32*c + r;
                run += p.tf[row*HD + d];
                p.H3[row*HD + d] = run / (float)(row + 1);
            }
        }
    } else if (bid == 1) {
        int d = tid & 63, g = tid >> 6;
        float s = 0.f;
        for (int r = g; r < NV; r += 4) s += p.cf4[r*HD + d];
        buf[tid] = s; __syncthreads();
        if (tid < 64) p.h4[tid] = buf[tid] + buf[tid+64] + buf[tid+128] + buf[tid+192];
    } else if (bid < 130) {
        int q = bid - 2, ks = q >> 5, t = q & 31;
        float* out = (ks == 0) ? p.Np0 : (ks == 1) ? p.Np1 : (ks == 2) ? p.Np2 : p.Np3;
        gemm_core(LdAdj{p.adj}, p.U, nullptr, out, DIM, ks*128, ks*128+128, 0,
                  (t>>2)*64, (t&3)*64, buf);
    } else if (bid < 194) {
        int w = (bid - 130) * 8 + (tid >> 5);
        int lane = tid & 31;
        float pr = 0.f;
        for (int j = lane; j < NV; j += 32) pr += (float)p.adj[w*NV + j] * p.E[j];
#pragma unroll
        for (int o = 16; o; o >>= 1) pr += __shfl_xor_sync(0xffffffffu, pr, o);
        if (lane == 0) p.Dinv[w] = 1.f / pr;
    } else {
        float (*sA)[68] = (float(*)[68])buf;
        float (*sB)[68] = (float(*)[68])(buf + 32*68);
        float* red = buf + 64*68;
        float* gsh = red + 256;
        int q0 = bid - 194;
        int b = q0 >> 2, qk = q0 & 3;
        int bi = (b >> 3) * 64, bj = (b & 7) * 64;
        int kbeg = qk * 64;
        int tx = tid & 15, ty = tid >> 4;
        int warp = tid >> 5, lane = tid & 31;

        float e[4][4];
        float m = ninf();
#pragma unroll
        for (int r = 0; r < 4; r++) {
            int i = bi + ty*4 + r;
            float4 s0 = *(const float4*)&p.Sp0[i*NV + bj + tx*4];
            float4 s1 = *(const float4*)&p.Sp1[i*NV + bj + tx*4];
            float4 s2 = *(const float4*)&p.Sp2[i*NV + bj + tx*4];
            float4 s3 = *(const float4*)&p.Sp3[i*NV + bj + tx*4];
            float sv[4] = { (s0.x+s1.x)+(s2.x+s3.x), (s0.y+s1.y)+(s2.y+s3.y),
                            (s0.z+s1.z)+(s2.z+s3.z), (s0.w+s1.w)+(s2.w+s3.w) };
#pragma unroll
            for (int c = 0; c < 4; c++) {
                if (i == bj + tx*4 + c) sv[c] = ninf();
                e[r][c] = sv[c];
                m = fmaxf(m, sv[c]);
            }
        }
        red[tid] = m; __syncthreads();
        for (int o = 128; o; o >>= 1) { if (tid < o) red[tid] = fmaxf(red[tid], red[tid+o]); __syncthreads(); }
        float M = red[0];
        __syncthreads();
        float se = 0.f;
#pragma unroll
        for (int r = 0; r < 4; r++)
#pragma unroll
            for (int c = 0; c < 4; c++) { float ev = expf(e[r][c] - M); e[r][c] = ev; se += ev; }
        red[tid] = se; __syncthreads();
        for (int o = 128; o; o >>= 1) { if (tid < o) red[tid] += red[tid+o]; __syncthreads(); }
        if (qk == 0 && tid == 0) { p.mb[b] = M; p.seb[b] = red[0]; }

        u64 eh[4][2];
#pragma unroll
        for (int r = 0; r < 4; r++) {
            eh[r][0] = pk2x(e[r][0]*0.5f, e[r][1]*0.5f);
            eh[r][1] = pk2x(e[r][2]*0.5f, e[r][3]*0.5f);
        }
        for (int k0 = kbeg; k0 < kbeg + 64; k0 += 32) {
#pragma unroll
            for (int q = 0; q < 8; q++) {
                int t = tid + q * 256;
                int i = t >> 5, k = t & 31;
                sA[k][i] = p.Aa[(bi + i) * DIM + k0 + k];
                sB[k][i] = p.Bb[(bj + i) * DIM + k0 + k];
            }
            __syncthreads();
#pragma unroll
            for (int k = 0; k < 32; k++) {
                float4 av = *(float4*)&sA[k][ty*4];
                u64 A0 = pk2(av.x), A1 = pk2(av.y), A2 = pk2(av.z), A3 = pk2(av.w);
                u64 B01 = f2u(*(float2*)&sB[k][tx*4]);
                u64 B23 = f2u(*(float2*)&sB[k][tx*4 + 2]);
                u64 c0 = 0ULL, c1 = 0ULL, c2 = 0ULL, c3 = 0ULL;
                rfma2(c0, A0, B01, eh[0][0]); rfma2(c0, A0, B23, eh[0][1]);
                rfma2(c1, A1, B01, eh[1][0]); rfma2(c1, A1, B23, eh[1][1]);
                rfma2(c2, A2, B01, eh[2][0]); rfma2(c2, A2, B23, eh[2][1]);
                rfma2(c3, A3, B01, eh[3][0]); rfma2(c3, A3, B23, eh[3][1]);
                u64 s01 = add2(c0, c1), s23 = add2(c2, c3);
                float plo, phi; upk(add2(s01, s23), plo, phi);
                float pk = plo + phi;
#pragma unroll
                for (int o = 16; o; o >>= 1) pk += __shfl_down_sync(0xffffffffu, pk, o);
                if (lane == 0) gsh[(k0 - kbeg + k) * 8 + warp] = pk;
            }
            __syncthreads();
        }
        if (tid < 64) {
            float s8 = 0.f;
#pragma unroll
            for (int w2 = 0; w2 < 8; w2++) s8 += gsh[tid * 8 + w2];
            p.gpart[b * DIM + kbeg + tid] = s8;
        }
    }
}

// ---------- Wave 5: [combiner first] + op = Hcat@Wf (K split 8), 257 CTAs ----------
struct W5P {
    const float *Np0, *Np1, *Np2, *Np3, *Dinv, *H3, *h4, *Wf;
    const float *mb, *seb, *gpart, *cew2, *ceb2, *bo;
    float* opp;
    float* bias2;
};
__global__ void __launch_bounds__(256) k_w5(W5P p) {
    __shared__ __align__(16) float buf[4352];
    int b = blockIdx.x, tid = threadIdx.x;
    if (b == 0) {
        float* sw = buf;
        float* red = buf + 64;
        float* ga = buf + 128;
        float* sH2 = buf + 384;
        __shared__ float sM, sInv;
        float mv = (tid < 64) ? p.mb[tid] : ninf();
        if (tid < 64) red[tid] = mv;
        __syncthreads();
        for (int o = 32; o; o >>= 1) { if (tid < o) red[tid] = fmaxf(red[tid], red[tid+o]); __syncthreads(); }
        if (tid == 0) sM = red[0];
        __syncthreads();
        float swv = 0.f;
        if (tid < 64) { swv = expf(mv - sM); sw[tid] = swv; red[tid] = p.seb[tid] * swv; }
        __syncthreads();
        for (int o = 32; o; o >>= 1) { if (tid < o) red[tid] += red[tid+o]; __syncthreads(); }
        if (tid == 0) sInv = 1.f / red[0];
        __syncthreads();
        float g = 0.f;
        for (int bb = 0; bb < 64; bb++) g += p.gpart[bb * DIM + tid] * sw[bb];
        ga[tid] = g * sInv;
        __syncthreads();
        if (tid < 64) {
            float s = 0.f;
            for (int k = 0; k < DIM; k++) s += ga[k] * p.cew2[k*HD + tid];
            sH2[tid] = s + p.ceb2[tid];
        }
        __syncthreads();
        float s = 0.f;
        for (int d = 0; d < HD; d++) s += sH2[d] * p.Wf[(256 + d)*DIM + tid];
        p.bias2[tid] = s + p.bo[tid];
    } else {
        int q0 = b - 1;
        int ks = q0 >> 5, t = q0 & 31;
        const int kb[8] = {0, 44, 88, 132, 176, 220, 320, 352};
        const int ke[8] = {44, 88, 132, 176, 220, 256, 352, 385};
        LdHcat ld{p.Np0, p.Np1, p.Np2, p.Np3, p.Dinv, p.H3, p.h4};
        gemm_core(ld, p.Wf, nullptr, p.opp + ks * (NV*DIM), DIM,
                  kb[ks], ke[ks], 0, (t>>2)*64, (t&3)*64, buf);
    }
}

// ---------- layernorm + elu: single-pass mean/var, warp-shuffle reductions ----------
struct LNP {
    const float* opp;
    const float *bias2, *g, *b;
    float* out;
};
__global__ void __launch_bounds__(256) k_lnelu(LNP p) {
    __shared__ float w1s[8], w2s[8];
    __shared__ float smu, srs;
    int i = blockIdx.x, t = threadIdx.x;
    int off = i*DIM + t;
    float x = p.bias2[t];
#pragma unroll
    for (int q = 0; q < 8; q++) x += p.opp[q * (NV*DIM) + off];
    float s1 = x, s2 = x * x;
#pragma unroll
    for (int o = 16; o; o >>= 1) {
        s1 += __shfl_xor_sync(0xffffffffu, s1, o);
        s2 += __shfl_xor_sync(0xffffffffu, s2, o);
    }
    int warp = t >> 5, lane = t & 31;
    if (lane == 0) { w1s[warp] = s1; w2s[warp] = s2; }
    __syncthreads();
    if (t == 0) {
        float a1 = 0.f, a2 = 0.f;
#pragma unroll
        for (int w = 0; w < 8; w++) { a1 += w1s[w]; a2 += w2s[w]; }
        float mu = a1 / (float)DIM;
        float var = a2 / (float)DIM - mu * mu;
        smu = mu;
        srs = rsqrtf(var + EPSLN);
    }
    __syncthreads();
    float y = (x - smu) * srs * p.g[t] + p.b[t];
    p.out[off] = (y > 0.f) ? y : expm1f(y);
}

extern "C" void kernel_launch(void* const* d_in, const int* in_sizes, int n_in,
                              void* d_out, int out_size) {
    const float* V      = (const float*)d_in[0];
    const int*   adj    = (const int*)d_in[1];
    const float* ph     = (const float*)d_in[2];
    const float* W1     = (const float*)d_in[3];
    const float* a_std1 = (const float*)d_in[5];
    const float* ce_w1  = (const float*)d_in[6];
    const float* ce_b1  = (const float*)d_in[7];
    const float* ce_w2  = (const float*)d_in[8];
    const float* ce_b2  = (const float*)d_in[9];
    const float* a_c0   = (const float*)d_in[10];
    const float* a_c1   = (const float*)d_in[11];
    const float* te_w1  = (const float*)d_in[12];
    const float* te_b1  = (const float*)d_in[13];
    const float* te_w2  = (const float*)d_in[14];
    const float* te_b2  = (const float*)d_in[15];
    const float* co_w1  = (const float*)d_in[18];
    const float* co_b1  = (const float*)d_in[19];
    const float* co_w2  = (const float*)d_in[20];
    const float* co_b2  = (const float*)d_in[21];
    const float* W2     = (const float*)d_in[24];
    const float* Wo     = (const float*)d_in[25];
    const float* bo     = (const float*)d_in[26];
    const float* ln_g   = (const float*)d_in[27];
    const float* ln_b   = (const float*)d_in[28];
    float* out = (float*)d_out;

    Scratch* s = nullptr;
    cudaGetSymbolAddress((void**)&s, g_s);

    W1P p1 = { V, ph, W1, ce_w1, ce_b1, te_w1, co_w1, ce_w2, a_c0, a_c1, W2, Wo, adj,
               s->Wh1, s->Aa, s->Bb, s->thp0, s->thp1, s->chp0, s->chp1, s->chp2, s->wc, s->Wf };
    k_w1<<<285, 256>>>(p1);

    W2P p2 = { s->Aa, s->Bb, s->wc,
               s->thp0, s->thp1, te_b1, te_w2, te_b2,
               s->chp0, s->chp1, s->chp2, co_b1, co_w2, co_b2,
               s->Wh1, a_std1,
               s->Sp[0], s->Sp[1], s->Sp[2], s->Sp[3], s->tf, s->cf4, s->E, s->U };
    k_w2<<<280, 256>>>(p2);

    W3P p3 = { s->Aa, s->Bb, s->Sp[0], s->Sp[1], s->Sp[2], s->Sp[3], s->U, s->E, s->tf, s->cf4, adj,
               s->mb, s->seb, s->gpart, s->Np0, s->Np1, s->Np2, s->Np3,
               s->Dinv, s->H3, s->h4 };
    k_w3<<<450, 256>>>(p3);

    W5P p5 = { s->Np0, s->Np1, s->Np2, s->Np3, s->Dinv, s->H3, s->h4, s->Wf,
               s->mb, s->seb, s->gpart, ce_w2, ce_b2, bo,
               s->opp[0], s->bias2 };
    k_w5<<<257, 256>>>(p5);

    LNP pl = { s->opp[0], s->bias2, ln_g, ln_b, out };
    k_lnelu<<<NV, 256>>>(pl);
}